// round 16
// baseline (speedup 1.0000x reference)
#include <cuda_runtime.h>
#include <cuda_bf16.h>
#include <cstdint>

#define DEVINL __device__ __forceinline__

constexpr int BB = 256;            // batch
constexpr int II = 512;            // input dim
constexpr int RR = 1024;           // hidden dim
constexpr int UU = 11;             // unroll length
constexpr int NSTEP = 10;          // steps that matter (step 10 is dead)
constexpr int OUTLD = UU * RR;     // output row stride
constexpr int PRELD = NSTEP * 4 * RR;

constexpr int BM  = 128;           // CTA m-tile
constexpr int BN  = 128;           // CTA n-tile = 4 gates x 32 r-cols
constexpr int KC  = 32;            // k-chunk (bf16 elems = 64 bytes)
constexpr int AW  = 20;            // smem row stride in words (16 data + 4 pad)
constexpr int NST = 3;             // pipeline stages
constexpr int WBLK = 4 * RR * RR;  // one weight block (elems)
constexpr int NCVT_CTAS = 20;      // shadow-convert CTAs in k_step (148 total)
constexpr int CVU = 16;            // convert unroll (MLP per thread)

struct SmemL {
    uint32_t As[NST][BM][AW];
    uint32_t Bs[NST][BN][AW];
};
constexpr int SMEM_DYN = (int)sizeof(SmemL);   // 61,440 B

// merged-convert region boundaries (float4 units)
constexpr int CV_N0 = BB * II / 4;
constexpr int CV_N1 = NSTEP * 4 * RR * II / 4;
constexpr int CV_N2 = NSTEP * WBLK / 4;
constexpr int CV_N3 = WBLK / 4;
constexpr int CV_C0 = CV_N0;
constexpr int CV_C1 = CV_C0 + CV_N1;
constexpr int CV_C2 = CV_C1 + CV_N2;
constexpr int CV_C3 = CV_C2 + CV_N3;
constexpr int CV_C4 = CV_C3 + CV_N3;

// ---- scratch (__device__ globals; no allocation allowed) ----
__device__ __align__(16) __nv_bfloat16 g_Wi0b[(size_t)NSTEP * 4 * RR * II];
__device__ __align__(16) __nv_bfloat16 g_Wh0b[(size_t)NSTEP * WBLK];
__device__ __align__(16) __nv_bfloat16 g_Wi1b[(size_t)NSTEP * WBLK];
__device__ __align__(16) __nv_bfloat16 g_Wh1b[(size_t)NSTEP * WBLK];
__device__ __align__(16) __nv_bfloat16 g_xb[BB * II];
__device__ __align__(16) __nv_bfloat16 g_h0b[2][BB * RR];
__device__ __align__(16) __nv_bfloat16 g_h1b[2][BB * RR];
__device__ __align__(16) float g_preX[(size_t)BB * PRELD];
__device__ __align__(16) float g_c0[BB * RR];
__device__ __align__(16) float g_c1[BB * RR];

DEVINL void cp16(void* s, const void* g) {
    uint32_t sa = (uint32_t)__cvta_generic_to_shared(s);
    asm volatile("cp.async.cg.shared.global [%0], [%1], 16;" :: "r"(sa), "l"(g));
}
DEVINL void cp_commit() { asm volatile("cp.async.commit_group;"); }
DEVINL void cp_wait0()  { asm volatile("cp.async.wait_group 0;"); }
DEVINL void cp_wait1()  { asm volatile("cp.async.wait_group 1;"); }

DEVINL void ldsm4(uint32_t& r0, uint32_t& r1, uint32_t& r2, uint32_t& r3,
                  const void* p) {
    uint32_t a = (uint32_t)__cvta_generic_to_shared(p);
    asm volatile("ldmatrix.sync.aligned.m8n8.x4.shared.b16 {%0,%1,%2,%3}, [%4];"
                 : "=r"(r0), "=r"(r1), "=r"(r2), "=r"(r3) : "r"(a));
}

DEVINL void mma16(float* d, const uint32_t* a, const uint32_t* b) {
    asm volatile(
        "mma.sync.aligned.m16n8k16.row.col.f32.bf16.bf16.f32 "
        "{%0,%1,%2,%3}, {%4,%5,%6,%7}, {%8,%9}, {%0,%1,%2,%3};"
        : "+f"(d[0]), "+f"(d[1]), "+f"(d[2]), "+f"(d[3])
        : "r"(a[0]), "r"(a[1]), "r"(a[2]), "r"(a[3]), "r"(b[0]), "r"(b[1]));
}

DEVINL float sigm(float x) { return 1.0f / (1.0f + expf(-x)); }

DEVINL uint2 pack_bf16x4(float4 v) {
    __nv_bfloat162 lo = __floats2bfloat162_rn(v.x, v.y);
    __nv_bfloat162 hi = __floats2bfloat162_rn(v.z, v.w);
    uint2 o;
    o.x = *reinterpret_cast<uint32_t*>(&lo);
    o.y = *reinterpret_cast<uint32_t*>(&hi);
    return o;
}

// bf16 TN GEMM body: CTA tile 128m x 128n (4 gates x 32 r), 512 thr = 16 warps
// (4m x 4n of 32m x 32n). W rows for gate g at nbase + g*gstride + r (r<32).
// Each warp spans all 4 gates x 8 r so the LSTM cell fuses in-register.
//   EPI 0: precompute -> acc + e0[col] + e1[col] into houtf (PreX, fp32)
//   EPI 1: layer0 cell -> base = PreX, state c0, write h0_next (bf16)
//   EPI 2: layer1 cell -> base = bi1+bh1, state c1, write h1 (fp32 out + bf16)
template<int EPI, int NPAIRS>
DEVINL void gemm_body(SmemL& sm, int m0, int nbase,
                      const __nv_bfloat16* __restrict__ A0, int lda0,
                      const __nv_bfloat16* __restrict__ W0,
                      const __nv_bfloat16* __restrict__ A1, int lda1,
                      const __nv_bfloat16* __restrict__ W1,
                      int K, int gstride,
                      const float* __restrict__ e0,
                      const float* __restrict__ e1,
                      float* __restrict__ cst,
                      float* __restrict__ houtf, int ldh,
                      __nv_bfloat16* __restrict__ houtb)
{
    const int tid  = threadIdx.x;
    const int warp = tid >> 5, lane = tid & 31;
    const int wm = warp >> 2, wn = warp & 3;       // 4m x 4n warps
    const int gid = lane >> 2, tig = lane & 3;

    const int lr = tid >> 2;                 // 0..127 (loader row)
    const int w  = tid & 3;                  // 16B segment

    // ldmatrix lane-derived coordinates
    const int a_row = 32 * wm + (lane & 15);                         // +16*mi
    const int a_wof = (lane >> 4) << 2;                              // +kw0
    const int b_row = ((lane >> 4) & 1) * 32 + 8 * wn + (lane & 7);  // +64*gp
    const int b_wof = ((lane >> 3) & 1) << 2;                        // +kw0

    const __nv_bfloat16* Ag[NPAIRS];
    const __nv_bfloat16* Wg[NPAIRS];
    int ldaP[NPAIRS];
    #pragma unroll
    for (int p = 0; p < NPAIRS; p++) {
        const __nv_bfloat16* A = (p == 0) ? A0 : A1;
        const __nv_bfloat16* W = (p == 0) ? W0 : W1;
        ldaP[p] = (p == 0) ? lda0 : lda1;
        Ag[p] = A + (size_t)(m0 + lr) * ldaP[p] + 8 * w;
        const int grow = nbase + (lr >> 5) * gstride + (lr & 31);    // gate, r
        Wg[p] = W + (size_t)grow * K + 8 * w;
    }

    const int nk = K / KC;
    const int T  = NPAIRS * nk;

    float acc[2][4][4];                       // [mi][gate][reg]
    #pragma unroll
    for (int a = 0; a < 2; a++)
        #pragma unroll
        for (int g = 0; g < 4; g++)
            #pragma unroll
            for (int c = 0; c < 4; c++) acc[a][g][c] = 0.0f;

    // --- prologue: chunks 0,1 (one A + one B cp16 per thread per chunk) ---
    #pragma unroll 1
    for (int ci = 0; ci < 2 && ci < T; ci++) {
        const int buf  = ci % NST;
        const int p    = (NPAIRS == 2 && ci >= nk) ? 1 : 0;
        const int koff = (p ? ci - nk : ci) * KC;
        cp16(&sm.As[buf][lr][4 * w], Ag[p] + koff);
        cp16(&sm.Bs[buf][lr][4 * w], Wg[p] + koff);
        cp_commit();
    }

    #pragma unroll 1
    for (int t = 0; t < T; t++) {
        if (t + 1 < T) cp_wait1(); else cp_wait0();
        __syncthreads();

        const int ci2 = t + 2;
        if (ci2 < T) {
            const int buf  = ci2 % NST;
            const int p    = (NPAIRS == 2 && ci2 >= nk) ? 1 : 0;
            const int koff = (p ? ci2 - nk : ci2) * KC;
            cp16(&sm.As[buf][lr][4 * w], Ag[p] + koff);
            cp16(&sm.Bs[buf][lr][4 * w], Wg[p] + koff);
            cp_commit();
        }

        const int buf = t % NST;
        #pragma unroll
        for (int ks = 0; ks < 2; ks++) {          // two k16 slices per KC=32
            const int kw0 = ks * 8;
            uint32_t ua[2][4];
            #pragma unroll
            for (int mi = 0; mi < 2; mi++)
                ldsm4(ua[mi][0], ua[mi][1], ua[mi][2], ua[mi][3],
                      &sm.As[buf][a_row + 16 * mi][kw0 + a_wof]);
            uint32_t ub[4][2];
            #pragma unroll
            for (int gp = 0; gp < 2; gp++)
                ldsm4(ub[2 * gp][0], ub[2 * gp][1],
                      ub[2 * gp + 1][0], ub[2 * gp + 1][1],
                      &sm.Bs[buf][b_row + 64 * gp][kw0 + b_wof]);
            #pragma unroll
            for (int mi = 0; mi < 2; mi++)
                #pragma unroll
                for (int g = 0; g < 4; g++)
                    mma16(acc[mi][g], ua[mi], ub[g]);
        }
    }

    // ---- epilogue ----
    #pragma unroll
    for (int mi = 0; mi < 2; mi++) {
        #pragma unroll
        for (int half = 0; half < 2; half++) {
            const int row = 32 * wm + 16 * mi + gid + 8 * half;
            const int b = m0 + row;
            #pragma unroll
            for (int cc = 0; cc < 2; cc++) {
                const int reg = 2 * half + cc;
                const int rl = 8 * wn + 2 * tig + cc;   // 0..31 within gate
                if constexpr (EPI == 0) {
                    #pragma unroll
                    for (int g = 0; g < 4; g++) {
                        const int col = nbase + g * gstride + rl;
                        houtf[(size_t)b * ldh + col] = acc[mi][g][reg] + e0[col] + e1[col];
                    }
                } else {
                    const int r = nbase + rl;
                    float pre[4];
                    #pragma unroll
                    for (int g = 0; g < 4; g++) {
                        float base;
                        if constexpr (EPI == 1)
                            base = e0[(size_t)b * PRELD + g * RR + r];
                        else
                            base = e0[g * RR + r] + e1[g * RR + r];
                        pre[g] = acc[mi][g][reg] + base;
                    }
                    const float cprev = cst[b * RR + r];
                    const float iv = sigm(pre[0]);
                    const float fv = sigm(pre[1]);
                    const float ov = sigm(pre[2]);
                    const float gv = tanhf(pre[3]);
                    const float cnew = fv * cprev + iv * gv;
                    const float hnew = ov * tanhf(cnew);
                    cst[b * RR + r] = cnew;
                    houtb[b * RR + r] = __float2bfloat16_rn(hnew);
                    if constexpr (EPI == 2)
                        houtf[(size_t)b * ldh + r] = hnew;
                }
            }
        }
    }
}

// ---- kernels ----

__global__ __launch_bounds__(512, 1)
void k_pre(const float* __restrict__ bi0, const float* __restrict__ bh0,
           float* __restrict__ preX)
{
    extern __shared__ SmemL smL[];
    const int rg = blockIdx.y * 32;               // 32 r-slots per CTA
    const int u = rg >> 10, rb = rg & 1023;
    const int nbase = u * 4096 + rb;
    gemm_body<0, 1>(smL[0], blockIdx.x * BM, nbase,
                    g_xb, II, g_Wi0b, nullptr, 0, nullptr,
                    II, RR, bi0, bh0, nullptr, preX, PRELD, nullptr);
}

__global__ __launch_bounds__(512, 1)
void k_l0(const __nv_bfloat16* __restrict__ h0cur, const __nv_bfloat16* __restrict__ Wh0u,
          const float* __restrict__ preXu, float* __restrict__ c0,
          __nv_bfloat16* __restrict__ h0nxt)
{
    extern __shared__ SmemL smL[];
    gemm_body<1, 1>(smL[0], blockIdx.x * BM, blockIdx.y * 32,
                    h0cur, RR, Wh0u, nullptr, 0, nullptr,
                    RR, RR, preXu, nullptr, c0, nullptr, 0, h0nxt);
}

__global__ __launch_bounds__(512, 1)
void k_l1(const __nv_bfloat16* __restrict__ h0cur, const __nv_bfloat16* __restrict__ Wi1u,
          const __nv_bfloat16* __restrict__ h1in, const __nv_bfloat16* __restrict__ Wh1u,
          const float* __restrict__ bi1u, const float* __restrict__ bh1u,
          float* __restrict__ c1, float* __restrict__ h1outf,
          __nv_bfloat16* __restrict__ h1outb)
{
    extern __shared__ SmemL smL[];
    gemm_body<2, 2>(smL[0], blockIdx.x * BM, blockIdx.y * 32,
                    h0cur, RR, Wi1u, h1in, RR, Wh1u,
                    RR, RR, bi1u, bh1u, c1, h1outf, OUTLD, h1outb);
}

// Combined step + shadow convert (grid (2, 74) = 148 CTAs = 1/SM):
//   y < 32   : L1(u)  (K=2048)
//   y 32..63 : L0(u+1) (K=1024)
//   y >= 64  : convert NEXT step's Wi1/Wh1 fp32->bf16 (batched MLP=CVU)
__global__ __launch_bounds__(512, 1)
void k_step(const __nv_bfloat16* __restrict__ h0cur, __nv_bfloat16* __restrict__ h0nxt,
            const __nv_bfloat16* __restrict__ Wi1u, const __nv_bfloat16* __restrict__ Wh1u,
            const float* __restrict__ bi1u, const float* __restrict__ bh1u,
            const __nv_bfloat16* __restrict__ h1in, float* __restrict__ h1outf,
            __nv_bfloat16* __restrict__ h1outb,
            const __nv_bfloat16* __restrict__ Wh0n, const float* __restrict__ preXn,
            float* __restrict__ c0, float* __restrict__ c1,
            const float4* __restrict__ cs0, uint2* __restrict__ cd0,
            const float4* __restrict__ cs1, uint2* __restrict__ cd1)
{
    const int y = blockIdx.y;
    if (y >= 64) {
        const int cid  = blockIdx.x * (NCVT_CTAS / 2) + (y - 64);   // 0..19
        const int nthr = NCVT_CTAS * 512;
        const int t0   = cid * 512 + threadIdx.x;
        const int n4   = WBLK / 4;
        #pragma unroll 1
        for (int b = 0; b < 2; b++) {
            const float4* s = (b == 0) ? cs0 : cs1;
            uint2*        d = (b == 0) ? cd0 : cd1;
            #pragma unroll 1
            for (int i = t0; i < n4; i += nthr * CVU) {
                float4 v[CVU];
                #pragma unroll
                for (int j = 0; j < CVU; j++) {
                    const int idx = i + j * nthr;
                    if (idx < n4) v[j] = s[idx];
                }
                #pragma unroll
                for (int j = 0; j < CVU; j++) {
                    const int idx = i + j * nthr;
                    if (idx < n4) d[idx] = pack_bf16x4(v[j]);
                }
            }
        }
        return;
    }
    extern __shared__ SmemL smL[];
    const int m0 = blockIdx.x * BM;
    if (y < 32) {
        gemm_body<2, 2>(smL[0], m0, y * 32,
                        h0cur, RR, Wi1u, h1in, RR, Wh1u,
                        RR, RR, bi1u, bh1u, c1, h1outf, OUTLD, h1outb);
    } else {
        gemm_body<1, 1>(smL[0], m0, (y - 32) * 32,
                        h0cur, RR, Wh0n, nullptr, 0, nullptr,
                        RR, RR, preXn, nullptr, c0, nullptr, 0, h0nxt);
    }
}

// One merged fp32->bf16 convert over all upfront regions:
//   [0,C0): x  [C0,C1): Wi0  [C1,C2): Wh0(all)  [C2,C3): Wi1[0]  [C3,C4): Wh1[0]
__global__ void k_cvt_all(const float4* __restrict__ sx,   uint2* __restrict__ dx,
                          const float4* __restrict__ si0,  uint2* __restrict__ di0,
                          const float4* __restrict__ sh0,  uint2* __restrict__ dh0,
                          const float4* __restrict__ si1,  uint2* __restrict__ di1,
                          const float4* __restrict__ sh1,  uint2* __restrict__ dh1)
{
    int i = blockIdx.x * blockDim.x + threadIdx.x;
    if (i >= CV_C4) return;
    const float4* s; uint2* d; int o;
    if      (i < CV_C0) { s = sx;  d = dx;  o = i; }
    else if (i < CV_C1) { s = si0; d = di0; o = i - CV_C0; }
    else if (i < CV_C2) { s = sh0; d = dh0; o = i - CV_C1; }
    else if (i < CV_C3) { s = si1; d = di1; o = i - CV_C2; }
    else                { s = sh1; d = dh1; o = i - CV_C3; }
    d[o] = pack_bf16x4(s[o]);
}

__global__ void init_states(const float* __restrict__ st, float* __restrict__ out) {
    int idx = blockIdx.x * blockDim.x + threadIdx.x;
    if (idx >= BB * RR) return;
    int b = idx >> 10, r = idx & (RR - 1);
    const float* s = st + (size_t)b * (4 * RR);
    g_h0b[0][idx] = __float2bfloat16_rn(s[r]);
    g_c0[idx]     = s[RR + r];
    float h1 = s[2 * RR + r];
    g_h1b[0][idx] = __float2bfloat16_rn(h1);
    out[(size_t)b * OUTLD + r] = h1;
    g_c1[idx]     = s[3 * RR + r];
}

extern "C" void kernel_launch(void* const* d_in, const int* in_sizes, int n_in,
                              void* d_out, int out_size)
{
    const float* x   = (const float*)d_in[0];
    const float* ini = (const float*)d_in[1];
    const float* Wi0 = (const float*)d_in[2];
    const float* bi0 = (const float*)d_in[3];
    const float* Wh0 = (const float*)d_in[4];
    const float* bh0 = (const float*)d_in[5];
    const float* Wi1 = (const float*)d_in[6];
    const float* bi1 = (const float*)d_in[7];
    const float* Wh1 = (const float*)d_in[8];
    const float* bh1 = (const float*)d_in[9];
    float* out = (float*)d_out;

    static bool attr_done = false;
    if (!attr_done) {
        cudaFuncSetAttribute(k_pre,  cudaFuncAttributeMaxDynamicSharedMemorySize, SMEM_DYN);
        cudaFuncSetAttribute(k_l0,   cudaFuncAttributeMaxDynamicSharedMemorySize, SMEM_DYN);
        cudaFuncSetAttribute(k_l1,   cudaFuncAttributeMaxDynamicSharedMemorySize, SMEM_DYN);
        cudaFuncSetAttribute(k_step, cudaFuncAttributeMaxDynamicSharedMemorySize, SMEM_DYN);
        attr_done = true;
    }

    float *preX, *c0, *c1;
    __nv_bfloat16 *wi0b, *wh0b, *wi1b, *wh1b, *xb, *h0b, *h1b;
    cudaGetSymbolAddress((void**)&preX, g_preX);
    cudaGetSymbolAddress((void**)&c0,   g_c0);
    cudaGetSymbolAddress((void**)&c1,   g_c1);
    cudaGetSymbolAddress((void**)&wi0b, g_Wi0b);
    cudaGetSymbolAddress((void**)&wh0b, g_Wh0b);
    cudaGetSymbolAddress((void**)&wi1b, g_Wi1b);
    cudaGetSymbolAddress((void**)&wh1b, g_Wh1b);
    cudaGetSymbolAddress((void**)&xb,   g_xb);
    cudaGetSymbolAddress((void**)&h0b,  g_h0b);
    cudaGetSymbolAddress((void**)&h1b,  g_h1b);

    auto h0p = [&](int i) { return h0b + (size_t)i * BB * RR; };
    auto h1p = [&](int i) { return h1b + (size_t)i * BB * RR; };

    // ---- single merged upfront convert ----
    k_cvt_all<<<(CV_C4 + 255) / 256, 256>>>(
        (const float4*)x,   (uint2*)xb,
        (const float4*)Wi0, (uint2*)wi0b,
        (const float4*)Wh0, (uint2*)wh0b,
        (const float4*)Wi1, (uint2*)wi1b,
        (const float4*)Wh1, (uint2*)wh1b);

    init_states<<<(BB * RR) / 256, 256>>>(ini, out);

    // PreX = x @ Wi0[0:10].T + bi0 + bh0
    k_pre<<<dim3(BB / BM, PRELD / 128), 512, SMEM_DYN>>>(bi0, bh0, preX);

    // L0(0)
    k_l0<<<dim3(BB / BM, RR / 32), 512, SMEM_DYN>>>(h0p(0), wh0b, preX, c0, h0p(1));

    // C(u) = L1(u) + L0(u+1) + shadow-convert(Wi1[u+1], Wh1[u+1]), u = 0..8
    for (int u = 0; u < NSTEP - 1; u++) {
        const size_t wo  = (size_t)u * WBLK;
        const size_t wn_ = (size_t)(u + 1) * WBLK;
        const size_t bo  = (size_t)u * 4 * RR;
        k_step<<<dim3(BB / BM, 64 + NCVT_CTAS / 2), 512, SMEM_DYN>>>(
            h0p((u + 1) & 1), h0p(u & 1),
            wi1b + wo, wh1b + wo, bi1 + bo, bh1 + bo,
            h1p(u & 1), out + (size_t)(u + 1) * RR, h1p((u + 1) & 1),
            wh0b + wn_, preX + (size_t)(u + 1) * 4 * RR,
            c0, c1,
            (const float4*)(Wi1 + wn_), (uint2*)(wi1b + wn_),
            (const float4*)(Wh1 + wn_), (uint2*)(wh1b + wn_));
    }

    // final L1(9)  (Wi1[9]/Wh1[9] converted inside k_step(8))
    {
        const int u = NSTEP - 1;
        const size_t wo = (size_t)u * WBLK;
        const size_t bo = (size_t)u * 4 * RR;
        k_l1<<<dim3(BB / BM, RR / 32), 512, SMEM_DYN>>>(
            h0p((u + 1) & 1), wi1b + wo,
            h1p(u & 1), wh1b + wo,
            bi1 + bo, bh1 + bo,
            c1, out + (size_t)(u + 1) * RR, h1p((u + 1) & 1));
    }
}

// round 17
// speedup vs baseline: 1.3517x; 1.3517x over previous
#include <cuda_runtime.h>
#include <cuda_bf16.h>
#include <cstdint>

#define DEVINL __device__ __forceinline__

constexpr int BB = 256;            // batch
constexpr int II = 512;            // input dim
constexpr int RR = 1024;           // hidden dim
constexpr int UU = 11;             // unroll length
constexpr int NSTEP = 10;          // steps that matter (step 10 is dead)
constexpr int OUTLD = UU * RR;     // output row stride
constexpr int PRELD = NSTEP * 4 * RR;

constexpr int BM  = 128;           // CTA m-tile
constexpr int KC  = 64;            // k-chunk (bf16 elems = 128 B per row)
constexpr int AW  = 36;            // smem row stride in words (32 data + 4 pad)
constexpr int NST = 3;             // pipeline stages
constexpr int WBLK = 4 * RR * RR;  // one weight block (elems)
constexpr int NCVT_CTAS = 40;      // shadow-convert CTAs in k_step (296 total)
constexpr int CVU = 16;            // convert unroll (MLP per thread)

struct SmemS {
    uint32_t As[NST][BM][AW];
    uint32_t Bs[NST][64][AW];
};
constexpr int SMEM_DYN = (int)sizeof(SmemS);   // 82,944 B -> 2 CTAs/SM

// merged-convert region boundaries (float4 units)
constexpr int CV_N0 = BB * II / 4;
constexpr int CV_N1 = NSTEP * 4 * RR * II / 4;
constexpr int CV_N2 = NSTEP * WBLK / 4;
constexpr int CV_N3 = WBLK / 4;
constexpr int CV_C0 = CV_N0;
constexpr int CV_C1 = CV_C0 + CV_N1;
constexpr int CV_C2 = CV_C1 + CV_N2;
constexpr int CV_C3 = CV_C2 + CV_N3;
constexpr int CV_C4 = CV_C3 + CV_N3;

// ---- scratch (__device__ globals; no allocation allowed) ----
__device__ __align__(16) __nv_bfloat16 g_Wi0b[(size_t)NSTEP * 4 * RR * II];
__device__ __align__(16) __nv_bfloat16 g_Wh0b[(size_t)NSTEP * WBLK];
__device__ __align__(16) __nv_bfloat16 g_Wi1b[(size_t)NSTEP * WBLK];
__device__ __align__(16) __nv_bfloat16 g_Wh1b[(size_t)NSTEP * WBLK];
__device__ __align__(16) __nv_bfloat16 g_xb[BB * II];
__device__ __align__(16) __nv_bfloat16 g_h0b[2][BB * RR];
__device__ __align__(16) __nv_bfloat16 g_h1b[2][BB * RR];
__device__ __align__(16) float g_preX[(size_t)BB * PRELD];
__device__ __align__(16) float g_c0[BB * RR];
__device__ __align__(16) float g_c1[BB * RR];

DEVINL void cp16(void* s, const void* g) {
    uint32_t sa = (uint32_t)__cvta_generic_to_shared(s);
    asm volatile("cp.async.cg.shared.global [%0], [%1], 16;" :: "r"(sa), "l"(g));
}
DEVINL void cp_commit() { asm volatile("cp.async.commit_group;"); }
DEVINL void cp_wait0()  { asm volatile("cp.async.wait_group 0;"); }
DEVINL void cp_wait1()  { asm volatile("cp.async.wait_group 1;"); }

DEVINL void ldsm4(uint32_t& r0, uint32_t& r1, uint32_t& r2, uint32_t& r3,
                  const void* p) {
    uint32_t a = (uint32_t)__cvta_generic_to_shared(p);
    asm volatile("ldmatrix.sync.aligned.m8n8.x4.shared.b16 {%0,%1,%2,%3}, [%4];"
                 : "=r"(r0), "=r"(r1), "=r"(r2), "=r"(r3) : "r"(a));
}

DEVINL void mma16(float* d, const uint32_t* a, const uint32_t* b) {
    asm volatile(
        "mma.sync.aligned.m16n8k16.row.col.f32.bf16.bf16.f32 "
        "{%0,%1,%2,%3}, {%4,%5,%6,%7}, {%8,%9}, {%0,%1,%2,%3};"
        : "+f"(d[0]), "+f"(d[1]), "+f"(d[2]), "+f"(d[3])
        : "r"(a[0]), "r"(a[1]), "r"(a[2]), "r"(a[3]), "r"(b[0]), "r"(b[1]));
}

DEVINL float sigm(float x) { return 1.0f / (1.0f + expf(-x)); }

DEVINL uint2 pack_bf16x4(float4 v) {
    __nv_bfloat162 lo = __floats2bfloat162_rn(v.x, v.y);
    __nv_bfloat162 hi = __floats2bfloat162_rn(v.z, v.w);
    uint2 o;
    o.x = *reinterpret_cast<uint32_t*>(&lo);
    o.y = *reinterpret_cast<uint32_t*>(&hi);
    return o;
}

// bf16 TN GEMM body: CTA tile 128m x 64n (4 gates x 16 r), 256 thr = 8 warps
// (4m x 2n of 32m x 32n). W rows for gate g at nbase + g*gstride + r.
// Loader (KC=64 = 128B/row, full-line wavefronts): 8 threads cover one row;
// 256 threads cover 32 rows/pass -> A (128 rows): 4 passes; B (64): 2 passes.
//   EPI 0: precompute -> acc + e0[col] + e1[col] into houtf (PreX, fp32)
//   EPI 1: layer0 cell -> base = PreX, state c0, write h0_next (bf16)
//   EPI 2: layer1 cell -> base = bi1+bh1, state c1, write h1 (fp32 out + bf16)
template<int EPI, int NPAIRS>
DEVINL void gemm_body(SmemS& sm, int m0, int nbase,
                      const __nv_bfloat16* __restrict__ A0, int lda0,
                      const __nv_bfloat16* __restrict__ W0,
                      const __nv_bfloat16* __restrict__ A1, int lda1,
                      const __nv_bfloat16* __restrict__ W1,
                      int K, int gstride,
                      const float* __restrict__ e0,
                      const float* __restrict__ e1,
                      float* __restrict__ cst,
                      float* __restrict__ houtf, int ldh,
                      __nv_bfloat16* __restrict__ houtb)
{
    const int tid  = threadIdx.x;
    const int warp = tid >> 5, lane = tid & 31;
    const int wm = warp >> 1, wn = warp & 1;       // 4m x 2n warps
    const int gid = lane >> 2, tig = lane & 3;

    const int lr = tid >> 3;                 // 0..31 (loader row within pass)
    const int w  = tid & 7;                  // 16B segment (8 per 128B row)

    // ldmatrix lane-derived coordinates (same as KC=32 version; within-row
    // word offsets, rows stride AW)
    const int a_row = 32 * wm + (lane & 15);                         // +16*mi
    const int a_wof = (lane >> 4) << 2;                              // +kw0
    const int b_row = ((lane >> 4) & 1) * 16 + 8 * wn + (lane & 7);  // +32*gp
    const int b_wof = ((lane >> 3) & 1) << 2;                        // +kw0

    const __nv_bfloat16* Ag[NPAIRS];
    const __nv_bfloat16* Wg[NPAIRS][2];
    int ldaP[NPAIRS];
    #pragma unroll
    for (int p = 0; p < NPAIRS; p++) {
        const __nv_bfloat16* A = (p == 0) ? A0 : A1;
        const __nv_bfloat16* W = (p == 0) ? W0 : W1;
        ldaP[p] = (p == 0) ? lda0 : lda1;
        Ag[p] = A + (size_t)(m0 + lr) * ldaP[p] + 8 * w;
        #pragma unroll
        for (int i = 0; i < 2; i++) {
            const int rowB = lr + 32 * i;
            const int grow = nbase + (rowB >> 4) * gstride + (rowB & 15);
            Wg[p][i] = W + (size_t)grow * K + 8 * w;
        }
    }

    const int nk = K / KC;
    const int T  = NPAIRS * nk;

    float acc[2][4][4];                       // [mi][gate][reg]
    #pragma unroll
    for (int a = 0; a < 2; a++)
        #pragma unroll
        for (int g = 0; g < 4; g++)
            #pragma unroll
            for (int c = 0; c < 4; c++) acc[a][g][c] = 0.0f;

    // --- prologue: chunks 0,1 ---
    #pragma unroll 1
    for (int ci = 0; ci < 2 && ci < T; ci++) {
        const int buf  = ci % NST;
        const int p    = (NPAIRS == 2 && ci >= nk) ? 1 : 0;
        const int koff = (p ? ci - nk : ci) * KC;
        #pragma unroll
        for (int i = 0; i < 4; i++)
            cp16(&sm.As[buf][lr + 32 * i][4 * w],
                 Ag[p] + (size_t)(32 * i) * ldaP[p] + koff);
        #pragma unroll
        for (int i = 0; i < 2; i++)
            cp16(&sm.Bs[buf][lr + 32 * i][4 * w], Wg[p][i] + koff);
        cp_commit();
    }

    #pragma unroll 1
    for (int t = 0; t < T; t++) {
        if (t + 1 < T) cp_wait1(); else cp_wait0();
        __syncthreads();

        const int ci2 = t + 2;
        if (ci2 < T) {
            const int buf  = ci2 % NST;
            const int p    = (NPAIRS == 2 && ci2 >= nk) ? 1 : 0;
            const int koff = (p ? ci2 - nk : ci2) * KC;
            #pragma unroll
            for (int i = 0; i < 4; i++)
                cp16(&sm.As[buf][lr + 32 * i][4 * w],
                     Ag[p] + (size_t)(32 * i) * ldaP[p] + koff);
            #pragma unroll
            for (int i = 0; i < 2; i++)
                cp16(&sm.Bs[buf][lr + 32 * i][4 * w], Wg[p][i] + koff);
            cp_commit();
        }

        const int buf = t % NST;
        #pragma unroll
        for (int ks = 0; ks < KC / 16; ks++) {    // 4 k16 slices per KC=64
            const int kw0 = ks * 8;
            uint32_t ua[2][4];
            #pragma unroll
            for (int mi = 0; mi < 2; mi++)
                ldsm4(ua[mi][0], ua[mi][1], ua[mi][2], ua[mi][3],
                      &sm.As[buf][a_row + 16 * mi][kw0 + a_wof]);
            uint32_t ub[4][2];
            #pragma unroll
            for (int gp = 0; gp < 2; gp++)
                ldsm4(ub[2 * gp][0], ub[2 * gp][1],
                      ub[2 * gp + 1][0], ub[2 * gp + 1][1],
                      &sm.Bs[buf][b_row + 32 * gp][kw0 + b_wof]);
            #pragma unroll
            for (int mi = 0; mi < 2; mi++)
                #pragma unroll
                for (int g = 0; g < 4; g++)
                    mma16(acc[mi][g], ua[mi], ub[g]);
        }
    }

    // ---- epilogue ----
    #pragma unroll
    for (int mi = 0; mi < 2; mi++) {
        #pragma unroll
        for (int half = 0; half < 2; half++) {
            const int row = 32 * wm + 16 * mi + gid + 8 * half;
            const int b = m0 + row;
            #pragma unroll
            for (int cc = 0; cc < 2; cc++) {
                const int reg = 2 * half + cc;
                const int rl = 8 * wn + 2 * tig + cc;   // 0..15
                if constexpr (EPI == 0) {
                    #pragma unroll
                    for (int g = 0; g < 4; g++) {
                        const int col = nbase + g * gstride + rl;
                        houtf[(size_t)b * ldh + col] = acc[mi][g][reg] + e0[col] + e1[col];
                    }
                } else {
                    const int r = nbase + rl;
                    float pre[4];
                    #pragma unroll
                    for (int g = 0; g < 4; g++) {
                        float base;
                        if constexpr (EPI == 1)
                            base = e0[(size_t)b * PRELD + g * RR + r];
                        else
                            base = e0[g * RR + r] + e1[g * RR + r];
                        pre[g] = acc[mi][g][reg] + base;
                    }
                    const float cprev = cst[b * RR + r];
                    const float iv = sigm(pre[0]);
                    const float fv = sigm(pre[1]);
                    const float ov = sigm(pre[2]);
                    const float gv = tanhf(pre[3]);
                    const float cnew = fv * cprev + iv * gv;
                    const float hnew = ov * tanhf(cnew);
                    cst[b * RR + r] = cnew;
                    houtb[b * RR + r] = __float2bfloat16_rn(hnew);
                    if constexpr (EPI == 2)
                        houtf[(size_t)b * ldh + r] = hnew;
                }
            }
        }
    }
}

// ---- kernels ----

__global__ __launch_bounds__(256, 2)
void k_pre(const float* __restrict__ bi0, const float* __restrict__ bh0,
           float* __restrict__ preX)
{
    extern __shared__ SmemS smS[];
    const int rg = blockIdx.y * 16;
    const int u = rg >> 10, rb = rg & 1023;
    const int nbase = u * 4096 + rb;
    gemm_body<0, 1>(smS[0], blockIdx.x * BM, nbase,
                    g_xb, II, g_Wi0b, nullptr, 0, nullptr,
                    II, RR, bi0, bh0, nullptr, preX, PRELD, nullptr);
}

__global__ __launch_bounds__(256, 2)
void k_l0(const __nv_bfloat16* __restrict__ h0cur, const __nv_bfloat16* __restrict__ Wh0u,
          const float* __restrict__ preXu, float* __restrict__ c0,
          __nv_bfloat16* __restrict__ h0nxt)
{
    extern __shared__ SmemS smS[];
    gemm_body<1, 1>(smS[0], blockIdx.x * BM, blockIdx.y * 16,
                    h0cur, RR, Wh0u, nullptr, 0, nullptr,
                    RR, RR, preXu, nullptr, c0, nullptr, 0, h0nxt);
}

__global__ __launch_bounds__(256, 2)
void k_l1(const __nv_bfloat16* __restrict__ h0cur, const __nv_bfloat16* __restrict__ Wi1u,
          const __nv_bfloat16* __restrict__ h1in, const __nv_bfloat16* __restrict__ Wh1u,
          const float* __restrict__ bi1u, const float* __restrict__ bh1u,
          float* __restrict__ c1, float* __restrict__ h1outf,
          __nv_bfloat16* __restrict__ h1outb)
{
    extern __shared__ SmemS smS[];
    gemm_body<2, 2>(smS[0], blockIdx.x * BM, blockIdx.y * 16,
                    h0cur, RR, Wi1u, h1in, RR, Wh1u,
                    RR, RR, bi1u, bh1u, c1, h1outf, OUTLD, h1outb);
}

// Combined step + shadow convert (grid (2, 148) = 296 CTAs = 2/SM wave):
//   y < 64   : L1(u)  (K=2048)
//   y 64..127: L0(u+1) (K=1024)
//   y >= 128 : convert NEXT step's Wi1/Wh1 fp32->bf16 (batched MLP=CVU)
__global__ __launch_bounds__(256, 2)
void k_step(const __nv_bfloat16* __restrict__ h0cur, __nv_bfloat16* __restrict__ h0nxt,
            const __nv_bfloat16* __restrict__ Wi1u, const __nv_bfloat16* __restrict__ Wh1u,
            const float* __restrict__ bi1u, const float* __restrict__ bh1u,
            const __nv_bfloat16* __restrict__ h1in, float* __restrict__ h1outf,
            __nv_bfloat16* __restrict__ h1outb,
            const __nv_bfloat16* __restrict__ Wh0n, const float* __restrict__ preXn,
            float* __restrict__ c0, float* __restrict__ c1,
            const float4* __restrict__ cs0, uint2* __restrict__ cd0,
            const float4* __restrict__ cs1, uint2* __restrict__ cd1)
{
    const int y = blockIdx.y;
    if (y >= 128) {
        const int cid  = blockIdx.x * (NCVT_CTAS / 2) + (y - 128);
        const int nthr = NCVT_CTAS * 256;
        const int t0   = cid * 256 + threadIdx.x;
        const int n4   = WBLK / 4;
        #pragma unroll 1
        for (int b = 0; b < 2; b++) {
            const float4* s = (b == 0) ? cs0 : cs1;
            uint2*        d = (b == 0) ? cd0 : cd1;
            #pragma unroll 1
            for (int i = t0; i < n4; i += nthr * CVU) {
                float4 v[CVU];
                #pragma unroll
                for (int j = 0; j < CVU; j++) {
                    const int idx = i + j * nthr;
                    if (idx < n4) v[j] = s[idx];
                }
                #pragma unroll
                for (int j = 0; j < CVU; j++) {
                    const int idx = i + j * nthr;
                    if (idx < n4) d[idx] = pack_bf16x4(v[j]);
                }
            }
        }
        return;
    }
    extern __shared__ SmemS smS[];
    const int m0 = blockIdx.x * BM;
    if (y < 64) {
        gemm_body<2, 2>(smS[0], m0, y * 16,
                        h0cur, RR, Wi1u, h1in, RR, Wh1u,
                        RR, RR, bi1u, bh1u, c1, h1outf, OUTLD, h1outb);
    } else {
        gemm_body<1, 1>(smS[0], m0, (y - 64) * 16,
                        h0cur, RR, Wh0n, nullptr, 0, nullptr,
                        RR, RR, preXn, nullptr, c0, nullptr, 0, h0nxt);
    }
}

// One merged fp32->bf16 convert over all upfront regions:
//   [0,C0): x  [C0,C1): Wi0  [C1,C2): Wh0(all)  [C2,C3): Wi1[0]  [C3,C4): Wh1[0]
__global__ void k_cvt_all(const float4* __restrict__ sx,   uint2* __restrict__ dx,
                          const float4* __restrict__ si0,  uint2* __restrict__ di0,
                          const float4* __restrict__ sh0,  uint2* __restrict__ dh0,
                          const float4* __restrict__ si1,  uint2* __restrict__ di1,
                          const float4* __restrict__ sh1,  uint2* __restrict__ dh1)
{
    int i = blockIdx.x * blockDim.x + threadIdx.x;
    if (i >= CV_C4) return;
    const float4* s; uint2* d; int o;
    if      (i < CV_C0) { s = sx;  d = dx;  o = i; }
    else if (i < CV_C1) { s = si0; d = di0; o = i - CV_C0; }
    else if (i < CV_C2) { s = sh0; d = dh0; o = i - CV_C1; }
    else if (i < CV_C3) { s = si1; d = di1; o = i - CV_C2; }
    else                { s = sh1; d = dh1; o = i - CV_C3; }
    d[o] = pack_bf16x4(s[o]);
}

__global__ void init_states(const float* __restrict__ st, float* __restrict__ out) {
    int idx = blockIdx.x * blockDim.x + threadIdx.x;
    if (idx >= BB * RR) return;
    int b = idx >> 10, r = idx & (RR - 1);
    const float* s = st + (size_t)b * (4 * RR);
    g_h0b[0][idx] = __float2bfloat16_rn(s[r]);
    g_c0[idx]     = s[RR + r];
    float h1 = s[2 * RR + r];
    g_h1b[0][idx] = __float2bfloat16_rn(h1);
    out[(size_t)b * OUTLD + r] = h1;
    g_c1[idx]     = s[3 * RR + r];
}

extern "C" void kernel_launch(void* const* d_in, const int* in_sizes, int n_in,
                              void* d_out, int out_size)
{
    const float* x   = (const float*)d_in[0];
    const float* ini = (const float*)d_in[1];
    const float* Wi0 = (const float*)d_in[2];
    const float* bi0 = (const float*)d_in[3];
    const float* Wh0 = (const float*)d_in[4];
    const float* bh0 = (const float*)d_in[5];
    const float* Wi1 = (const float*)d_in[6];
    const float* bi1 = (const float*)d_in[7];
    const float* Wh1 = (const float*)d_in[8];
    const float* bh1 = (const float*)d_in[9];
    float* out = (float*)d_out;

    static bool attr_done = false;
    if (!attr_done) {
        cudaFuncSetAttribute(k_pre,  cudaFuncAttributeMaxDynamicSharedMemorySize, SMEM_DYN);
        cudaFuncSetAttribute(k_l0,   cudaFuncAttributeMaxDynamicSharedMemorySize, SMEM_DYN);
        cudaFuncSetAttribute(k_l1,   cudaFuncAttributeMaxDynamicSharedMemorySize, SMEM_DYN);
        cudaFuncSetAttribute(k_step, cudaFuncAttributeMaxDynamicSharedMemorySize, SMEM_DYN);
        attr_done = true;
    }

    float *preX, *c0, *c1;
    __nv_bfloat16 *wi0b, *wh0b, *wi1b, *wh1b, *xb, *h0b, *h1b;
    cudaGetSymbolAddress((void**)&preX, g_preX);
    cudaGetSymbolAddress((void**)&c0,   g_c0);
    cudaGetSymbolAddress((void**)&c1,   g_c1);
    cudaGetSymbolAddress((void**)&wi0b, g_Wi0b);
    cudaGetSymbolAddress((void**)&wh0b, g_Wh0b);
    cudaGetSymbolAddress((void**)&wi1b, g_Wi1b);
    cudaGetSymbolAddress((void**)&wh1b, g_Wh1b);
    cudaGetSymbolAddress((void**)&xb,   g_xb);
    cudaGetSymbolAddress((void**)&h0b,  g_h0b);
    cudaGetSymbolAddress((void**)&h1b,  g_h1b);

    auto h0p = [&](int i) { return h0b + (size_t)i * BB * RR; };
    auto h1p = [&](int i) { return h1b + (size_t)i * BB * RR; };

    // ---- single merged upfront convert ----
    k_cvt_all<<<(CV_C4 + 255) / 256, 256>>>(
        (const float4*)x,   (uint2*)xb,
        (const float4*)Wi0, (uint2*)wi0b,
        (const float4*)Wh0, (uint2*)wh0b,
        (const float4*)Wi1, (uint2*)wi1b,
        (const float4*)Wh1, (uint2*)wh1b);

    init_states<<<(BB * RR) / 256, 256>>>(ini, out);

    // PreX = x @ Wi0[0:10].T + bi0 + bh0
    k_pre<<<dim3(BB / BM, PRELD / 64), 256, SMEM_DYN>>>(bi0, bh0, preX);

    // L0(0)
    k_l0<<<dim3(BB / BM, RR / 16), 256, SMEM_DYN>>>(h0p(0), wh0b, preX, c0, h0p(1));

    // C(u) = L1(u) + L0(u+1) + shadow-convert(Wi1[u+1], Wh1[u+1]), u = 0..8
    for (int u = 0; u < NSTEP - 1; u++) {
        const size_t wo  = (size_t)u * WBLK;
        const size_t wn_ = (size_t)(u + 1) * WBLK;
        const size_t bo  = (size_t)u * 4 * RR;
        k_step<<<dim3(BB / BM, 128 + NCVT_CTAS / 2), 256, SMEM_DYN>>>(
            h0p((u + 1) & 1), h0p(u & 1),
            wi1b + wo, wh1b + wo, bi1 + bo, bh1 + bo,
            h1p(u & 1), out + (size_t)(u + 1) * RR, h1p((u + 1) & 1),
            wh0b + wn_, preX + (size_t)(u + 1) * 4 * RR,
            c0, c1,
            (const float4*)(Wi1 + wn_), (uint2*)(wi1b + wn_),
            (const float4*)(Wh1 + wn_), (uint2*)(wh1b + wn_));
    }

    // final L1(9)  (Wi1[9]/Wh1[9] converted inside k_step(8))
    {
        const int u = NSTEP - 1;
        const size_t wo = (size_t)u * WBLK;
        const size_t bo = (size_t)u * 4 * RR;
        k_l1<<<dim3(BB / BM, RR / 16), 256, SMEM_DYN>>>(
            h0p((u + 1) & 1), wi1b + wo,
            h1p(u & 1), wh1b + wo,
            bi1 + bo, bh1 + bo,
            c1, out + (size_t)(u + 1) * RR, h1p((u + 1) & 1));
    }
}